// round 14
// baseline (speedup 1.0000x reference)
#include <cuda_runtime.h>
#include <math.h>

#define TW 2560
#define TMM 32
#define BB 4
#define HH 896
#define G3 2688
#define NB 256
#define DP 512
#define NCTA 112
#define UPC 8
#define RPC 24
#define CH 32

__device__ __align__(16) float g_gi0f[TMM*BB*384];
__device__ __align__(16) float g_gi0b[TMM*BB*384];
__device__ __align__(16) float g_enc0[TMM*BB*256];
__device__ __align__(16) float g_gi1f[TMM*BB*384];
__device__ __align__(16) float g_gi1b[TMM*BB*384];
__device__ __align__(16) float g_enc1[TMM*BB*256];
__device__ __align__(16) float g_GE[NB*G3];
__device__ __align__(16) float g_Gc[TMM*BB*G3];
__device__ __align__(16) int   g_qw[TW*BB];
__device__ __align__(16) int   g_qt[TW*BB];
__device__ __align__(16) float g_WdT[DP*NB];
__device__ __align__(16) float g_WT0f[384*128];
__device__ __align__(16) float g_WT0b[384*128];
__device__ __align__(16) float g_WT1f[384*128];
__device__ __align__(16) float g_WT1b[384*128];
__device__ __align__(16) float g_h[2*HH*BB];
__device__ __align__(16) float g_H[(size_t)TW*BB*HH];
__device__ __align__(16) float g_o[(size_t)TW*BB*DP];
__device__ unsigned g_bar;
__device__ double   g_nll;

__device__ __forceinline__ int quant(float v) {
    int q = (int)floorf((v + 1.0f) * 128.0f);
    return max(0, min(255, q));
}

// reset per-launch state (graph replays must be deterministic)
__global__ void init_kernel() {
    int idx = blockIdx.x * blockDim.x + threadIdx.x;
    if (idx < 2*HH*BB) g_h[idx] = 0.0f;
    if (idx == 0) { g_bar = 0u; g_nll = 0.0; }
}

__global__ void prep_kernel(const float* __restrict__ y, const float* __restrict__ Wd) {
    int idx = blockIdx.x * blockDim.x + threadIdx.x;
    if (idx < TW*BB) {
        int t = idx / BB, b = idx % BB;
        g_qt[idx] = quant(y[idx]);
        float w = (t == 0) ? 0.0f : y[(t-1)*BB + b];
        g_qw[idx] = quant(w);
    }
    if (idx < DP*NB) {
        int k = idx / NB, j = idx % NB;
        g_WdT[idx] = Wd[j*DP + k];
    }
}

// transpose the 4 encoder Whh matrices (384x128) to k-major (128x384)
__global__ void prep2_kernel(const float* __restrict__ W0f, const float* __restrict__ W0b,
                             const float* __restrict__ W1f, const float* __restrict__ W1b) {
    int idx = blockIdx.x * blockDim.x + threadIdx.x;
    if (idx < 384*128) {
        int r = idx >> 7, k = idx & 127;
        g_WT0f[k*384 + r] = W0f[idx];
        g_WT0b[k*384 + r] = W0b[idx];
        g_WT1f[k*384 + r] = W1f[idx];
        g_WT1b[k*384 + r] = W1b[idx];
    }
}

// Trivially-correct GEMM: C[m][r] = sum_k A[m*K+k] * W[r*wstride+k] (+bias[r]).
__global__ void matvec_rows(const float* __restrict__ A,
                            const float* __restrict__ W, int wstride,
                            const float* __restrict__ bias,
                            float* __restrict__ C, int M, int R, int K)
{
    int idx = blockIdx.x * blockDim.x + threadIdx.x;
    if (idx >= M*R) return;
    int m = idx / R, r = idx - m*R;
    const float* a = A + (size_t)m * K;
    const float* w = W + (size_t)r * wstride;
    float s = bias ? bias[r] : 0.0f;
    for (int k = 0; k < K; k++) s += a[k] * w[k];
    C[(size_t)m * R + r] = s;
}

// C[M,N] = gelu(A[M,896] @ B[N,896]^T + bias). 64x64 tile, 256 threads, static SMEM.
__global__ void __launch_bounds__(256) gemm_gelu(
    const float* __restrict__ A, const float* __restrict__ B,
    const float* __restrict__ bias, float* __restrict__ C)
{
    __shared__ float As[16][65];
    __shared__ float Bs[16][65];
    const int K = HH, ldab = HH, ldc = DP;
    int tid = threadIdx.x;
    int n0 = blockIdx.x * 64, m0 = blockIdx.y * 64;
    int tx = tid & 15, ty = tid >> 4;

    float acc[4][4];
#pragma unroll
    for (int i = 0; i < 4; i++)
#pragma unroll
        for (int j = 0; j < 4; j++) acc[i][j] = 0.0f;

    int lrow = tid >> 2;
    int lk4  = (tid & 3) * 4;

    for (int kt = 0; kt < K; kt += 16) {
#pragma unroll
        for (int q = 0; q < 4; q++) {
            As[lk4 + q][lrow] = A[(size_t)(m0 + lrow) * ldab + kt + lk4 + q];
            Bs[lk4 + q][lrow] = B[(size_t)(n0 + lrow) * ldab + kt + lk4 + q];
        }
        __syncthreads();
#pragma unroll
        for (int k = 0; k < 16; k++) {
            float a[4], b[4];
#pragma unroll
            for (int i = 0; i < 4; i++) a[i] = As[k][ty*4 + i];
#pragma unroll
            for (int j = 0; j < 4; j++) b[j] = Bs[k][tx*4 + j];
#pragma unroll
            for (int i = 0; i < 4; i++)
#pragma unroll
                for (int j = 0; j < 4; j++) acc[i][j] += a[i] * b[j];
        }
        __syncthreads();
    }
#pragma unroll
    for (int j = 0; j < 4; j++) {
        float bv = bias[n0 + tx*4 + j];
#pragma unroll
        for (int i = 0; i < 4; i++) {
            float v = acc[i][j] + bv;
            v = 0.5f * v * (1.0f + erff(v * 0.70710678118654752f));
            C[(size_t)(m0 + ty*4 + i) * ldc + n0 + tx*4 + j] = v;
        }
    }
}

// encoder GRU scan (fwd+bwd fused): grid (BB, 2), 384 threads, static SMEM only.
__global__ void __launch_bounds__(384) enc_scan2(
    const float* __restrict__ giF, const float* __restrict__ giB,
    const float* __restrict__ WTF, const float* __restrict__ WTB,
    const float* __restrict__ bhhF, const float* __restrict__ bhhB,
    float* __restrict__ out)
{
    __shared__ float h_sm[128];
    __shared__ float gh[384];
    int b = blockIdx.x;
    int dir = blockIdx.y;
    const float* gi  = dir ? giB  : giF;
    const float* WT  = dir ? WTB  : WTF;
    const float* bhh = dir ? bhhB : bhhF;
    int outOff = dir ? 128 : 0;
    int i = threadIdx.x;

    if (i < 128) h_sm[i] = 0.0f;
    __syncthreads();

    for (int s = 0; s < 32; s++) {
        int t = dir ? (31 - s) : s;
        float a = 0.0f;
        const float* w = WT + i;
#pragma unroll 8
        for (int k = 0; k < 128; k++)
            a += __ldg(w + k*384) * h_sm[k];
        gh[i] = a;
        __syncthreads();
        if (i < 128) {
            const float* gp = gi + (size_t)(t*BB + b) * 384;
            float r = 1.0f / (1.0f + expf(-(gp[i]       + gh[i]       + bhh[i])));
            float z = 1.0f / (1.0f + expf(-(gp[128 + i] + gh[128 + i] + bhh[128 + i])));
            float n = tanhf(gp[256 + i] + r * (gh[256 + i] + bhh[256 + i]));
            float hnew = (1.0f - z) * n + z * h_sm[i];
            h_sm[i] = hnew;
            out[(size_t)(t*BB + b) * 256 + outOff + i] = hnew;
        }
        __syncthreads();
    }
}

// wav GRU chunk: CH=32 steps per plain launch (31 internal grid barriers).
// 112 CTAs x 256 threads, sole resident kernel => all co-resident.
// Whh slice in registers; h exchange via L2 (__stcg/__ldcg) + monotonic barrier.
// Barrier is starvation-free: a CTA ALWAYS atomicAdds; bail only skips waiting.
__global__ void wav_chunk(const float* __restrict__ Whh, const float* __restrict__ bhh, int t0)
{
    __shared__ float4 hs4[HH];
    __shared__ float  gh_smf[RPC*BB];
    int tid = threadIdx.x, cta = blockIdx.x;
    int wid = tid >> 5, lane = tid & 31;
    int r0 = wid * 3;
    int c = t0 / CH;

    float wreg[3][28];
#pragma unroll
    for (int i = 0; i < 3; i++) {
        int lr = r0 + i;
        int g = lr >> 3, u = lr & 7;
        const float* wrow = Whh + (size_t)(g*HH + cta*UPC + u) * HH;
#pragma unroll
        for (int j = 0; j < 28; j++) wreg[i][j] = wrow[lane + 32*j];
    }

    int gu = tid >> 2, gb = tid & 3;
    float bhr = 0.f, bhz = 0.f, bhn = 0.f; int jg = 0;
    if (tid < 32) {
        jg = cta*UPC + gu;
        bhr = bhh[jg]; bhz = bhh[HH + jg]; bhn = bhh[2*HH + jg];
    }
    __syncthreads();

    float4* gh4 = (float4*)gh_smf;

    for (int s = 0; s < CH; s++) {
        int t = t0 + s;
        int cur = t & 1;
        int tm = t / 80;

        float gir = 0.f, giz = 0.f, gin = 0.f;
        if (tid < 32) {
            int q = g_qw[t*BB + gb];
            const float* ge = g_GE + (size_t)q * G3;
            const float* gc = g_Gc + (size_t)(tm*BB + gb) * G3;
            gir = ge[jg]        + gc[jg];
            giz = ge[HH + jg]   + gc[HH + jg];
            gin = ge[2*HH + jg] + gc[2*HH + jg];
        }
        // stage h_t: L2-only loads (cross-SM data)
        const float4* hg = (const float4*)(g_h + cur * HH * BB);
        for (int idx = tid; idx < HH; idx += 256) hs4[idx] = __ldcg(hg + idx);
        __syncthreads();

        float4 a0 = {0,0,0,0}, a1 = {0,0,0,0}, a2 = {0,0,0,0};
#pragma unroll
        for (int j = 0; j < 28; j++) {
            float4 h4 = hs4[lane + 32*j];
            float w0 = wreg[0][j], w1 = wreg[1][j], w2 = wreg[2][j];
            a0.x += w0*h4.x; a0.y += w0*h4.y; a0.z += w0*h4.z; a0.w += w0*h4.w;
            a1.x += w1*h4.x; a1.y += w1*h4.y; a1.z += w1*h4.z; a1.w += w1*h4.w;
            a2.x += w2*h4.x; a2.y += w2*h4.y; a2.z += w2*h4.z; a2.w += w2*h4.w;
        }
#pragma unroll
        for (int off = 16; off; off >>= 1) {
            a0.x += __shfl_xor_sync(0xffffffffu, a0.x, off);
            a0.y += __shfl_xor_sync(0xffffffffu, a0.y, off);
            a0.z += __shfl_xor_sync(0xffffffffu, a0.z, off);
            a0.w += __shfl_xor_sync(0xffffffffu, a0.w, off);
            a1.x += __shfl_xor_sync(0xffffffffu, a1.x, off);
            a1.y += __shfl_xor_sync(0xffffffffu, a1.y, off);
            a1.z += __shfl_xor_sync(0xffffffffu, a1.z, off);
            a1.w += __shfl_xor_sync(0xffffffffu, a1.w, off);
            a2.x += __shfl_xor_sync(0xffffffffu, a2.x, off);
            a2.y += __shfl_xor_sync(0xffffffffu, a2.y, off);
            a2.z += __shfl_xor_sync(0xffffffffu, a2.z, off);
            a2.w += __shfl_xor_sync(0xffffffffu, a2.w, off);
        }
        if (lane == 0) { gh4[r0] = a0; gh4[r0+1] = a1; gh4[r0+2] = a2; }
        __syncthreads();

        if (tid < 32) {
            float ghr = gh_smf[gu*4 + gb];
            float ghz = gh_smf[(UPC + gu)*4 + gb];
            float ghn = gh_smf[(2*UPC + gu)*4 + gb];
            float rg = 1.0f / (1.0f + expf(-(gir + ghr + bhr)));
            float zg = 1.0f / (1.0f + expf(-(giz + ghz + bhz)));
            float ng = tanhf(gin + rg * (ghn + bhn));
            float4 hold4 = hs4[jg];
            float hold = (gb == 0) ? hold4.x : (gb == 1) ? hold4.y : (gb == 2) ? hold4.z : hold4.w;
            float hnew = (1.0f - zg) * ng + zg * hold;
            __stcg(g_h + (cur^1) * HH * BB + jg*4 + gb, hnew);
            g_H[(size_t)(t*BB + gb) * HH + jg] = hnew;
        }
        __syncthreads();
        // inter-step grid barrier, except after the chunk's last step
        // (the kernel boundary provides that sync)
        if (s < CH-1) {
            if (tid == 0) {
                __threadfence();
                atomicAdd(&g_bar, 1u);          // ALWAYS contribute
                unsigned target = (unsigned)NCTA * (unsigned)(c*(CH-1) + s + 1);
                unsigned guard = 0;
                while (*((volatile unsigned*)&g_bar) < target) {
                    if (++guard > 100000u) break;   // bail skips wait only
                }
                __threadfence();
            }
            __syncthreads();
        }
    }
}

// fused logits + log_softmax + NLL, 8 rows/block, static SMEM
__global__ void __launch_bounds__(256) nll_kernel(const float* __restrict__ bd)
{
    __shared__ float o_sm[8*DP];
    __shared__ float lg[8*NB];
    int tid = threadIdx.x;
    int m0 = blockIdx.x * 8;

    const float4* op = (const float4*)(g_o + (size_t)m0 * DP);
    float4* os4 = (float4*)o_sm;
    for (int idx = tid; idx < 8*DP/4; idx += 256) os4[idx] = op[idx];
    __syncthreads();

    float acc[8];
    float bdv = bd[tid];
#pragma unroll
    for (int r = 0; r < 8; r++) acc[r] = bdv;

    for (int k = 0; k < DP; k += 4) {
        float w0 = g_WdT[(k+0)*NB + tid];
        float w1 = g_WdT[(k+1)*NB + tid];
        float w2 = g_WdT[(k+2)*NB + tid];
        float w3 = g_WdT[(k+3)*NB + tid];
#pragma unroll
        for (int r = 0; r < 8; r++) {
            float4 o4 = *(const float4*)&o_sm[r*DP + k];
            acc[r] += w0*o4.x + w1*o4.y + w2*o4.z + w3*o4.w;
        }
    }
#pragma unroll
    for (int r = 0; r < 8; r++) lg[r*NB + tid] = acc[r];
    __syncthreads();

    int wid = tid >> 5, lane = tid & 31;
    {
        int r = wid;
        float m = -1e30f;
#pragma unroll
        for (int i = 0; i < 8; i++) m = fmaxf(m, lg[r*NB + lane + i*32]);
#pragma unroll
        for (int off = 16; off; off >>= 1) m = fmaxf(m, __shfl_xor_sync(0xffffffffu, m, off));
        float s = 0.f;
#pragma unroll
        for (int i = 0; i < 8; i++) s += expf(lg[r*NB + lane + i*32] - m);
#pragma unroll
        for (int off = 16; off; off >>= 1) s += __shfl_xor_sync(0xffffffffu, s, off);
        if (lane == 0) {
            int row = m0 + r;
            int tgt = g_qt[row];
            float nllr = (m + logf(s)) - lg[r*NB + tgt];
            atomicAdd(&g_nll, (double)nllr);
        }
    }
}

// finalize with 8-bit liveness diagnostic:
// WT0f(1) gi0f(2) enc0(4) enc1(8) GE(16) Gc(32) H(64) o(128).
// F==255 -> NLL; else out = 1000 + F.
__global__ void finalize_kernel(float* out) {
    float p[8] = {0,0,0,0,0,0,0,0};
#pragma unroll
    for (int i = 0; i < 8; i++) {
        p[0] += fabsf(g_WT0f[i * 6143 + 5]);
        p[1] += fabsf(g_gi0f[i * 6143 + 9]);
        p[2] += fabsf(g_enc0[i * 4093 + 3]);
        p[3] += fabsf(g_enc1[i * 4093 + 3]);
        p[4] += fabsf(g_GE[(size_t)i * 86011 + 7]);
        p[5] += fabsf(g_Gc[(size_t)i * 43007 + 1]);
        p[6] += fabsf(g_H[(size_t)i * 1111111 + 13]);
        p[7] += fabsf(g_o[(size_t)i * 654321 + 11]);
    }
    int F = 0;
#pragma unroll
    for (int i = 0; i < 8; i++) if (p[i] > 0.f) F |= (1 << i);
    if (F == 255) out[0] = (float)(g_nll / (double)(TW * BB));
    else          out[0] = 1000.0f + (float)F;
}

extern "C" void kernel_launch(void* const* d_in, const int* in_sizes, int n_in,
                              void* d_out, int out_size)
{
    const float* x        = (const float*)d_in[0];
    const float* y        = (const float*)d_in[1];
    const float* m0f_Wih  = (const float*)d_in[2];
    const float* m0f_Whh  = (const float*)d_in[3];
    const float* m0f_bih  = (const float*)d_in[4];
    const float* m0f_bhh  = (const float*)d_in[5];
    const float* m0b_Wih  = (const float*)d_in[6];
    const float* m0b_Whh  = (const float*)d_in[7];
    const float* m0b_bih  = (const float*)d_in[8];
    const float* m0b_bhh  = (const float*)d_in[9];
    const float* m1f_Wih  = (const float*)d_in[10];
    const float* m1f_Whh  = (const float*)d_in[11];
    const float* m1f_bih  = (const float*)d_in[12];
    const float* m1f_bhh  = (const float*)d_in[13];
    const float* m1b_Wih  = (const float*)d_in[14];
    const float* m1b_Whh  = (const float*)d_in[15];
    const float* m1b_bih  = (const float*)d_in[16];
    const float* m1b_bhh  = (const float*)d_in[17];
    const float* w_Wih    = (const float*)d_in[18];
    const float* w_Whh    = (const float*)d_in[19];
    const float* w_bih    = (const float*)d_in[20];
    const float* w_bhh    = (const float*)d_in[21];
    const float* Wp       = (const float*)d_in[22];
    const float* bp       = (const float*)d_in[23];
    const float* E        = (const float*)d_in[24];
    const float* Wd       = (const float*)d_in[25];
    const float* bd       = (const float*)d_in[26];

    // CRITICAL: __device__ symbols used as host-side launch args resolve to the
    // HOST shadow address (silently dereferenceable on GB300 via ATS!). Fetch
    // the true device addresses. Pure query: capture-safe, allocation-free.
    float *pgi0f, *pgi0b, *penc0, *pgi1f, *pgi1b, *penc1, *pGE, *pGc;
    float *pWT0f, *pWT0b, *pWT1f, *pWT1b, *pH, *po;
    cudaGetSymbolAddress((void**)&pgi0f, g_gi0f);
    cudaGetSymbolAddress((void**)&pgi0b, g_gi0b);
    cudaGetSymbolAddress((void**)&penc0, g_enc0);
    cudaGetSymbolAddress((void**)&pgi1f, g_gi1f);
    cudaGetSymbolAddress((void**)&pgi1b, g_gi1b);
    cudaGetSymbolAddress((void**)&penc1, g_enc1);
    cudaGetSymbolAddress((void**)&pGE,   g_GE);
    cudaGetSymbolAddress((void**)&pGc,   g_Gc);
    cudaGetSymbolAddress((void**)&pWT0f, g_WT0f);
    cudaGetSymbolAddress((void**)&pWT0b, g_WT0b);
    cudaGetSymbolAddress((void**)&pWT1f, g_WT1f);
    cudaGetSymbolAddress((void**)&pWT1b, g_WT1b);
    cudaGetSymbolAddress((void**)&pH,    g_H);
    cudaGetSymbolAddress((void**)&po,    g_o);

    init_kernel<<<(2*HH*BB + 255)/256, 256>>>();
    prep_kernel<<<(DP*NB + 255)/256, 256>>>(y, Wd);
    prep2_kernel<<<(384*128 + 255)/256, 256>>>(m0f_Whh, m0b_Whh, m1f_Whh, m1b_Whh);

    // encoder layer 0: gi = x @ Wih^T + bih   (M=128, R=384, K=80)
    matvec_rows<<<(128*384 + 255)/256, 256>>>(x, m0f_Wih, 80, m0f_bih, pgi0f, 128, 384, 80);
    matvec_rows<<<(128*384 + 255)/256, 256>>>(x, m0b_Wih, 80, m0b_bih, pgi0b, 128, 384, 80);
    enc_scan2<<<dim3(BB,2), 384>>>(pgi0f, pgi0b, pWT0f, pWT0b, m0f_bhh, m0b_bhh, penc0);

    // encoder layer 1 (K=256)
    matvec_rows<<<(128*384 + 255)/256, 256>>>(penc0, m1f_Wih, 256, m1f_bih, pgi1f, 128, 384, 256);
    matvec_rows<<<(128*384 + 255)/256, 256>>>(penc0, m1b_Wih, 256, m1b_bih, pgi1b, 128, 384, 256);
    enc_scan2<<<dim3(BB,2), 384>>>(pgi1f, pgi1b, pWT1f, pWT1b, m1f_bhh, m1b_bhh, penc1);

    // wav GRU input-projection lookup tables
    matvec_rows<<<(256*G3 + 255)/256, 256>>>(E, w_Wih, 512, (const float*)0, pGE, 256, G3, 256);
    matvec_rows<<<(128*G3 + 255)/256, 256>>>(penc1, w_Wih + 256, 512, w_bih, pGc, 128, G3, 256);

    // recurrence: 80 chunk launches x 32 steps (31 internal barriers each)
    for (int c = 0; c < TW/CH; c++)
        wav_chunk<<<NCTA, 256>>>(w_Whh, w_bhh, c*CH);

    // projection + GELU: o = gelu(H @ Wp^T + bp)
    gemm_gelu<<<dim3(DP/64, (TW*BB)/64), 256>>>(pH, Wp, bp, po);

    // logits + NLL
    nll_kernel<<<(TW*BB)/8, 256>>>(bd);
    finalize_kernel<<<1, 1>>>((float*)d_out);
}

// round 15
// speedup vs baseline: 1.2880x; 1.2880x over previous
#include <cuda_runtime.h>
#include <math.h>

#define TW 2560
#define TMM 32
#define BB 4
#define HH 896
#define G3 2688
#define NB 256
#define DP 512
#define NCTA 112
#define UPC 8
#define RPC 24
#define CH 32

__device__ __align__(16) float g_gi0f[TMM*BB*384];
__device__ __align__(16) float g_gi0b[TMM*BB*384];
__device__ __align__(16) float g_enc0[TMM*BB*256];
__device__ __align__(16) float g_gi1f[TMM*BB*384];
__device__ __align__(16) float g_gi1b[TMM*BB*384];
__device__ __align__(16) float g_enc1[TMM*BB*256];
__device__ __align__(16) float g_GE[NB*G3];
__device__ __align__(16) float g_Gc[TMM*BB*G3];
__device__ __align__(16) int   g_qw[TW*BB];
__device__ __align__(16) int   g_qt[TW*BB];
__device__ __align__(16) float g_WdT[DP*NB];
__device__ __align__(16) float g_WT0f[384*128];
__device__ __align__(16) float g_WT0b[384*128];
__device__ __align__(16) float g_WT1f[384*128];
__device__ __align__(16) float g_WT1b[384*128];
__device__ __align__(16) float g_WT[512*G3];          // w_Wih transposed (k-major)
__device__ __align__(16) float g_h[2*HH*BB];
__device__ __align__(16) float g_H[(size_t)TW*BB*HH];
__device__ __align__(16) float g_o[(size_t)TW*BB*DP];
__device__ unsigned g_bar;
__device__ double   g_nll;

__device__ __forceinline__ int quant(float v) {
    int q = (int)floorf((v + 1.0f) * 128.0f);
    return max(0, min(255, q));
}

// ---- launch 0: fused init + quantize + all weight transposes ------------
__global__ void prep_all(const float* __restrict__ y, const float* __restrict__ Wd,
                         const float* __restrict__ W0f, const float* __restrict__ W0b,
                         const float* __restrict__ W1f, const float* __restrict__ W1b,
                         const float* __restrict__ wWih)
{
    int idx = blockIdx.x * blockDim.x + threadIdx.x;
    if (idx == 0) { g_bar = 0u; g_nll = 0.0; }
    if (idx < 2*HH*BB) g_h[idx] = 0.0f;
    if (idx < TW*BB) {
        int t = idx / BB, b = idx % BB;
        g_qt[idx] = quant(y[idx]);
        float w = (t == 0) ? 0.0f : y[(t-1)*BB + b];
        g_qw[idx] = quant(w);
    }
    if (idx < DP*NB) {
        int k = idx / NB, j = idx % NB;
        g_WdT[idx] = Wd[j*DP + k];
    }
    if (idx < 384*128) {
        int r = idx >> 7, k = idx & 127;
        g_WT0f[k*384 + r] = W0f[idx];
        g_WT0b[k*384 + r] = W0b[idx];
        g_WT1f[k*384 + r] = W1f[idx];
        g_WT1b[k*384 + r] = W1b[idx];
    }
    if (idx < G3*512) {
        int r = idx >> 9, k = idx & 511;
        g_WT[(size_t)k*G3 + r] = wWih[idx];
    }
}

// ---- launch 1: layer-0 input projections (y=0 fwd, y=1 bwd) + GE (y=2) ----
__global__ void __launch_bounds__(256) mv0(const float* __restrict__ x,
                                           const float* __restrict__ Wf, const float* __restrict__ bf,
                                           const float* __restrict__ Wb, const float* __restrict__ bb,
                                           const float* __restrict__ E)
{
    int y = blockIdx.y, gx = blockIdx.x, tid = threadIdx.x;
    __shared__ float a_sm[8][256];
    if (y < 2) {
        int idx = gx*256 + tid;
        if (idx >= 128*384) return;
        int m = idx / 384, r = idx - m*384;
        const float* W = (y ? Wb : Wf) + r*80;
        const float* a = x + m*80;
        float s = (y ? bb : bf)[r];
        for (int k = 0; k < 80; k++) s += a[k] * W[k];
        (y ? g_gi0b : g_gi0f)[idx] = s;
    } else {
        // GE[m][r] = E[m] . wWih[r, 0:256]  via transposed g_WT (coalesced)
        int mt = gx / 11, rt = gx - mt*11;
        int m0 = mt * 8;
#pragma unroll
        for (int i = 0; i < 8; i++) a_sm[i][tid] = E[(m0+i)*256 + tid];
        __syncthreads();
        int r = rt*256 + tid;
        if (r >= G3) return;
        float acc[8] = {0,0,0,0,0,0,0,0};
        for (int k = 0; k < 256; k++) {
            float wv = g_WT[(size_t)k*G3 + r];
#pragma unroll
            for (int i = 0; i < 8; i++) acc[i] += a_sm[i][k] * wv;
        }
#pragma unroll
        for (int i = 0; i < 8; i++) g_GE[(size_t)(m0+i)*G3 + r] = acc[i];
    }
}

// ---- launches 2,4: encoder GRU scan (fwd+bwd fused), layer selected ------
__global__ void __launch_bounds__(384) enc_scan2(int layer,
    const float* __restrict__ bhhF, const float* __restrict__ bhhB)
{
    __shared__ float h_sm[128];
    __shared__ float gh[384];
    int b = blockIdx.x;
    int dir = blockIdx.y;
    const float* gi  = layer ? (dir ? g_gi1b : g_gi1f) : (dir ? g_gi0b : g_gi0f);
    const float* WT  = layer ? (dir ? g_WT1b : g_WT1f) : (dir ? g_WT0b : g_WT0f);
    const float* bhh = dir ? bhhB : bhhF;
    float* out = layer ? g_enc1 : g_enc0;
    int outOff = dir ? 128 : 0;
    int i = threadIdx.x;

    if (i < 128) h_sm[i] = 0.0f;
    __syncthreads();

    for (int s = 0; s < 32; s++) {
        int t = dir ? (31 - s) : s;
        float a = 0.0f;
        const float* w = WT + i;
#pragma unroll 8
        for (int k = 0; k < 128; k++)
            a += __ldg(w + k*384) * h_sm[k];
        gh[i] = a;
        __syncthreads();
        if (i < 128) {
            const float* gp = gi + (size_t)(t*BB + b) * 384;
            float r = 1.0f / (1.0f + expf(-(gp[i]       + gh[i]       + bhh[i])));
            float z = 1.0f / (1.0f + expf(-(gp[128 + i] + gh[128 + i] + bhh[128 + i])));
            float n = tanhf(gp[256 + i] + r * (gh[256 + i] + bhh[256 + i]));
            float hnew = (1.0f - z) * n + z * h_sm[i];
            h_sm[i] = hnew;
            out[(size_t)(t*BB + b) * 256 + outOff + i] = hnew;
        }
        __syncthreads();
    }
}

// ---- launch 3: layer-1 input projections (reads g_enc0 directly) ---------
__global__ void __launch_bounds__(256) mv1(const float* __restrict__ Wf, const float* __restrict__ bf,
                                           const float* __restrict__ Wb, const float* __restrict__ bb)
{
    int y = blockIdx.y;
    int idx = blockIdx.x*256 + threadIdx.x;
    if (idx >= 128*384) return;
    int m = idx / 384, r = idx - m*384;
    const float* W = (y ? Wb : Wf) + r*256;
    const float* a = g_enc0 + m*256;
    float s = (y ? bb : bf)[r];
    for (int k = 0; k < 256; k++) s += a[k] * W[k];
    (y ? g_gi1b : g_gi1f)[idx] = s;
}

// ---- launch 5: Gc lookup table (reads g_enc1, g_WT rows 256..511) --------
__global__ void __launch_bounds__(256) mvGc(const float* __restrict__ w_bih)
{
    __shared__ float a_sm[8][256];
    int gx = blockIdx.x, tid = threadIdx.x;
    int mt = gx / 11, rt = gx - mt*11;
    int m0 = mt * 8;
#pragma unroll
    for (int i = 0; i < 8; i++) a_sm[i][tid] = g_enc1[(m0+i)*256 + tid];
    __syncthreads();
    int r = rt*256 + tid;
    if (r >= G3) return;
    float bv = w_bih[r];
    float acc[8] = {bv,bv,bv,bv,bv,bv,bv,bv};
    for (int k = 0; k < 256; k++) {
        float wv = g_WT[(size_t)(256+k)*G3 + r];
#pragma unroll
        for (int i = 0; i < 8; i++) acc[i] += a_sm[i][k] * wv;
    }
#pragma unroll
    for (int i = 0; i < 8; i++) g_Gc[(size_t)(m0+i)*G3 + r] = acc[i];
}

// ---- launches 6..85: wav GRU chunks (CH=32 steps, 31 internal barriers) ---
// 112 CTAs x 256 threads (sole resident kernel). Whh slice in registers.
// Release/acquire barrier: red.release by tid0, acquire-poll by warp 0 only.
// gi gather for step t+1 overlaps the barrier wait.
__global__ void wav_chunk(const float* __restrict__ Whh, const float* __restrict__ bhh, int t0)
{
    __shared__ float4 hs4[HH];
    __shared__ float  gh_smf[RPC*BB];
    int tid = threadIdx.x, cta = blockIdx.x;
    int wid = tid >> 5, lane = tid & 31;
    int r0 = wid * 3;
    int c = t0 / CH;

    float wreg[3][28];
#pragma unroll
    for (int i = 0; i < 3; i++) {
        int lr = r0 + i;
        int g = lr >> 3, u = lr & 7;
        const float* wrow = Whh + (size_t)(g*HH + cta*UPC + u) * HH;
#pragma unroll
        for (int j = 0; j < 28; j++) wreg[i][j] = wrow[lane + 32*j];
    }

    int gu = tid >> 2, gb = tid & 3;
    float bhr = 0.f, bhz = 0.f, bhn = 0.f; int jg = 0;
    float gir = 0.f, giz = 0.f, gin = 0.f;
    if (tid < 32) {
        jg = cta*UPC + gu;
        bhr = bhh[jg]; bhz = bhh[HH + jg]; bhn = bhh[2*HH + jg];
        // gi for the first step of this chunk
        int q = g_qw[t0*BB + gb];
        const float* ge = g_GE + (size_t)q * G3;
        const float* gc = g_Gc + (size_t)(t0/80*BB + gb) * G3;
        gir = ge[jg]        + gc[jg];
        giz = ge[HH + jg]   + gc[HH + jg];
        gin = ge[2*HH + jg] + gc[2*HH + jg];
    }
    __syncthreads();

    float4* gh4 = (float4*)gh_smf;

    for (int s = 0; s < CH; s++) {
        int t = t0 + s;
        int cur = t & 1;

        // stage h_t (L2; fresh by barrier/kernel-boundary + acquire)
        const float4* hg = (const float4*)(g_h + cur * HH * BB);
        for (int idx = tid; idx < HH; idx += 256) hs4[idx] = __ldcg(hg + idx);
        __syncthreads();

        float4 a0 = {0,0,0,0}, a1 = {0,0,0,0}, a2 = {0,0,0,0};
#pragma unroll
        for (int j = 0; j < 28; j++) {
            float4 h4 = hs4[lane + 32*j];
            float w0 = wreg[0][j], w1 = wreg[1][j], w2 = wreg[2][j];
            a0.x += w0*h4.x; a0.y += w0*h4.y; a0.z += w0*h4.z; a0.w += w0*h4.w;
            a1.x += w1*h4.x; a1.y += w1*h4.y; a1.z += w1*h4.z; a1.w += w1*h4.w;
            a2.x += w2*h4.x; a2.y += w2*h4.y; a2.z += w2*h4.z; a2.w += w2*h4.w;
        }
#pragma unroll
        for (int off = 16; off; off >>= 1) {
            a0.x += __shfl_xor_sync(0xffffffffu, a0.x, off);
            a0.y += __shfl_xor_sync(0xffffffffu, a0.y, off);
            a0.z += __shfl_xor_sync(0xffffffffu, a0.z, off);
            a0.w += __shfl_xor_sync(0xffffffffu, a0.w, off);
            a1.x += __shfl_xor_sync(0xffffffffu, a1.x, off);
            a1.y += __shfl_xor_sync(0xffffffffu, a1.y, off);
            a1.z += __shfl_xor_sync(0xffffffffu, a1.z, off);
            a1.w += __shfl_xor_sync(0xffffffffu, a1.w, off);
            a2.x += __shfl_xor_sync(0xffffffffu, a2.x, off);
            a2.y += __shfl_xor_sync(0xffffffffu, a2.y, off);
            a2.z += __shfl_xor_sync(0xffffffffu, a2.z, off);
            a2.w += __shfl_xor_sync(0xffffffffu, a2.w, off);
        }
        if (lane == 0) { gh4[r0] = a0; gh4[r0+1] = a1; gh4[r0+2] = a2; }
        __syncthreads();

        if (tid < 32) {
            float ghr = gh_smf[gu*4 + gb];
            float ghz = gh_smf[(UPC + gu)*4 + gb];
            float ghn = gh_smf[(2*UPC + gu)*4 + gb];
            float rg = 1.0f / (1.0f + expf(-(gir + ghr + bhr)));
            float zg = 1.0f / (1.0f + expf(-(giz + ghz + bhz)));
            float ng = tanhf(gin + rg * (ghn + bhn));
            float4 hold4 = hs4[jg];
            float hold = (gb == 0) ? hold4.x : (gb == 1) ? hold4.y : (gb == 2) ? hold4.z : hold4.w;
            float hnew = (1.0f - zg) * ng + zg * hold;
            __stcg(g_h + (cur^1) * HH * BB + jg*4 + gb, hnew);
            g_H[(size_t)(t*BB + gb) * HH + jg] = hnew;
        }
        __syncthreads();

        if (s < CH-1) {
            if (tid < 32) {
                if (tid == 0) {
                    unsigned one = 1u;
                    asm volatile("red.release.gpu.global.add.u32 [%0], %1;"
                                 :: "l"(&g_bar), "r"(one) : "memory");
                }
                // overlap: gather gi for step t+1 while waiting
                {
                    int tn = t + 1;
                    int q = g_qw[tn*BB + gb];
                    const float* ge = g_GE + (size_t)q * G3;
                    const float* gc = g_Gc + (size_t)(tn/80*BB + gb) * G3;
                    gir = ge[jg]        + gc[jg];
                    giz = ge[HH + jg]   + gc[HH + jg];
                    gin = ge[2*HH + jg] + gc[2*HH + jg];
                }
                unsigned target = (unsigned)NCTA * (unsigned)(c*(CH-1) + s + 1);
                unsigned v = 0, guard = 0;
                do {
                    asm volatile("ld.acquire.gpu.global.u32 %0, [%1];"
                                 : "=r"(v) : "l"(&g_bar) : "memory");
                } while (v < target && ++guard < 1000000u);
            }
            __syncthreads();
        }
    }
}

// ---- launch 86: projection + GELU, 128x64 tiles --------------------------
__global__ void __launch_bounds__(256) gemm_gelu(const float* __restrict__ B,
                                                 const float* __restrict__ bias)
{
    __shared__ float As[16][132];
    __shared__ float Bs[16][68];
    int tid = threadIdx.x;
    int n0 = blockIdx.x * 64, m0 = blockIdx.y * 128;
    int tx = tid & 15, ty = tid >> 4;

    float acc[8][4];
#pragma unroll
    for (int i = 0; i < 8; i++)
#pragma unroll
        for (int j = 0; j < 4; j++) acc[i][j] = 0.0f;

    int ar = tid >> 1, ak = (tid & 1) * 8;
    int br = tid >> 2, bk = (tid & 3) * 4;

    for (int kt = 0; kt < HH; kt += 16) {
        {
            const float* ap = g_H + (size_t)(m0 + ar) * HH + kt + ak;
            float4 v0 = *(const float4*)ap;
            float4 v1 = *(const float4*)(ap + 4);
            As[ak+0][ar] = v0.x; As[ak+1][ar] = v0.y;
            As[ak+2][ar] = v0.z; As[ak+3][ar] = v0.w;
            As[ak+4][ar] = v1.x; As[ak+5][ar] = v1.y;
            As[ak+6][ar] = v1.z; As[ak+7][ar] = v1.w;
        }
        {
            float4 v = *(const float4*)(B + (size_t)(n0 + br) * HH + kt + bk);
            Bs[bk+0][br] = v.x; Bs[bk+1][br] = v.y;
            Bs[bk+2][br] = v.z; Bs[bk+3][br] = v.w;
        }
        __syncthreads();
#pragma unroll
        for (int k = 0; k < 16; k++) {
            float a[8], b[4];
#pragma unroll
            for (int i = 0; i < 8; i++) a[i] = As[k][ty*8 + i];
#pragma unroll
            for (int j = 0; j < 4; j++) b[j] = Bs[k][tx*4 + j];
#pragma unroll
            for (int i = 0; i < 8; i++)
#pragma unroll
                for (int j = 0; j < 4; j++) acc[i][j] += a[i] * b[j];
        }
        __syncthreads();
    }
#pragma unroll
    for (int j = 0; j < 4; j++) {
        float bv = bias[n0 + tx*4 + j];
#pragma unroll
        for (int i = 0; i < 8; i++) {
            float v = acc[i][j] + bv;
            v = 0.5f * v * (1.0f + erff(v * 0.70710678118654752f));
            g_o[(size_t)(m0 + ty*8 + i) * DP + n0 + tx*4 + j] = v;
        }
    }
}

// ---- launch 87: fused logits + log_softmax + NLL --------------------------
__global__ void __launch_bounds__(256) nll_kernel(const float* __restrict__ bd)
{
    __shared__ float o_sm[8*DP];
    __shared__ float lg[8*NB];
    int tid = threadIdx.x;
    int m0 = blockIdx.x * 8;

    const float4* op = (const float4*)(g_o + (size_t)m0 * DP);
    float4* os4 = (float4*)o_sm;
    for (int idx = tid; idx < 8*DP/4; idx += 256) os4[idx] = op[idx];
    __syncthreads();

    float acc[8];
    float bdv = bd[tid];
#pragma unroll
    for (int r = 0; r < 8; r++) acc[r] = bdv;

    for (int k = 0; k < DP; k += 4) {
        float w0 = g_WdT[(k+0)*NB + tid];
        float w1 = g_WdT[(k+1)*NB + tid];
        float w2 = g_WdT[(k+2)*NB + tid];
        float w3 = g_WdT[(k+3)*NB + tid];
#pragma unroll
        for (int r = 0; r < 8; r++) {
            float4 o4 = *(const float4*)&o_sm[r*DP + k];
            acc[r] += w0*o4.x + w1*o4.y + w2*o4.z + w3*o4.w;
        }
    }
#pragma unroll
    for (int r = 0; r < 8; r++) lg[r*NB + tid] = acc[r];
    __syncthreads();

    int wid = tid >> 5, lane = tid & 31;
    {
        int r = wid;
        float m = -1e30f;
#pragma unroll
        for (int i = 0; i < 8; i++) m = fmaxf(m, lg[r*NB + lane + i*32]);
#pragma unroll
        for (int off = 16; off; off >>= 1) m = fmaxf(m, __shfl_xor_sync(0xffffffffu, m, off));
        float s = 0.f;
#pragma unroll
        for (int i = 0; i < 8; i++) s += expf(lg[r*NB + lane + i*32] - m);
#pragma unroll
        for (int off = 16; off; off >>= 1) s += __shfl_xor_sync(0xffffffffu, s, off);
        if (lane == 0) {
            int row = m0 + r;
            int tgt = g_qt[row];
            float nllr = (m + logf(s)) - lg[r*NB + tgt];
            atomicAdd(&g_nll, (double)nllr);
        }
    }
}

// ---- launch 88: finalize with 8-bit liveness diagnostic --------------------
// WT0f(1) gi0f(2) enc0(4) enc1(8) GE(16) Gc(32) H(64) o(128); 255 -> NLL.
__global__ void finalize_kernel(float* out) {
    float p[8] = {0,0,0,0,0,0,0,0};
#pragma unroll
    for (int i = 0; i < 8; i++) {
        p[0] += fabsf(g_WT0f[i * 6143 + 5]);
        p[1] += fabsf(g_gi0f[i * 6143 + 9]);
        p[2] += fabsf(g_enc0[i * 4093 + 3]);
        p[3] += fabsf(g_enc1[i * 4093 + 3]);
        p[4] += fabsf(g_GE[(size_t)i * 86011 + 7]);
        p[5] += fabsf(g_Gc[(size_t)i * 43007 + 1]);
        p[6] += fabsf(g_H[(size_t)i * 1111111 + 13]);
        p[7] += fabsf(g_o[(size_t)i * 654321 + 11]);
    }
    int F = 0;
#pragma unroll
    for (int i = 0; i < 8; i++) if (p[i] > 0.f) F |= (1 << i);
    if (F == 255) out[0] = (float)(g_nll / (double)(TW * BB));
    else          out[0] = 1000.0f + (float)F;
}

extern "C" void kernel_launch(void* const* d_in, const int* in_sizes, int n_in,
                              void* d_out, int out_size)
{
    const float* x        = (const float*)d_in[0];
    const float* y        = (const float*)d_in[1];
    const float* m0f_Wih  = (const float*)d_in[2];
    const float* m0f_Whh  = (const float*)d_in[3];
    const float* m0f_bih  = (const float*)d_in[4];
    const float* m0f_bhh  = (const float*)d_in[5];
    const float* m0b_Wih  = (const float*)d_in[6];
    const float* m0b_Whh  = (const float*)d_in[7];
    const float* m0b_bih  = (const float*)d_in[8];
    const float* m0b_bhh  = (const float*)d_in[9];
    const float* m1f_Wih  = (const float*)d_in[10];
    const float* m1f_Whh  = (const float*)d_in[11];
    const float* m1f_bih  = (const float*)d_in[12];
    const float* m1f_bhh  = (const float*)d_in[13];
    const float* m1b_Wih  = (const float*)d_in[14];
    const float* m1b_Whh  = (const float*)d_in[15];
    const float* m1b_bih  = (const float*)d_in[16];
    const float* m1b_bhh  = (const float*)d_in[17];
    const float* w_Wih    = (const float*)d_in[18];
    const float* w_Whh    = (const float*)d_in[19];
    const float* w_bih    = (const float*)d_in[20];
    const float* w_bhh    = (const float*)d_in[21];
    const float* Wp       = (const float*)d_in[22];
    const float* bp       = (const float*)d_in[23];
    const float* E        = (const float*)d_in[24];
    const float* Wd       = (const float*)d_in[25];
    const float* bd       = (const float*)d_in[26];

    // launch 0: everything data-independent
    prep_all<<<(G3*512 + 255)/256, 256>>>(y, Wd, m0f_Whh, m0b_Whh, m1f_Whh, m1b_Whh, w_Wih);
    // launch 1: layer-0 gi (f+b) and GE table
    mv0<<<dim3(352, 3), 256>>>(x, m0f_Wih, m0f_bih, m0b_Wih, m0b_bih, E);
    // launch 2: encoder scan layer 0
    enc_scan2<<<dim3(BB, 2), 384>>>(0, m0f_bhh, m0b_bhh);
    // launch 3: layer-1 gi (f+b)
    mv1<<<dim3(192, 2), 256>>>(m1f_Wih, m1f_bih, m1b_Wih, m1b_bih);
    // launch 4: encoder scan layer 1
    enc_scan2<<<dim3(BB, 2), 384>>>(1, m1f_bhh, m1b_bhh);
    // launch 5: Gc table
    mvGc<<<176, 256>>>(w_bih);
    // launches 6..85: recurrence (ncu profiles launch 6 = first wav_chunk)
    for (int c = 0; c < TW/CH; c++)
        wav_chunk<<<NCTA, 256>>>(w_Whh, w_bhh, c*CH);
    // launch 86: projection + GELU
    gemm_gelu<<<dim3(DP/64, (TW*BB)/128), 256>>>(Wp, bp);
    // launch 87: logits + NLL
    nll_kernel<<<(TW*BB)/8, 256>>>(bd);
    // launch 88: finalize
    finalize_kernel<<<1, 1>>>((float*)d_out);
}

// round 16
// speedup vs baseline: 1.6794x; 1.3039x over previous
#include <cuda_runtime.h>
#include <math.h>

#define TW 2560
#define TMM 32
#define BB 4
#define HH 896
#define G3 2688
#define NB 256
#define DP 512
#define NCTA 112
#define UPC 8
#define RPC 24
#define CH 32

__device__ __align__(16) float g_gi0f[TMM*BB*384];
__device__ __align__(16) float g_gi0b[TMM*BB*384];
__device__ __align__(16) float g_enc0[TMM*BB*256];
__device__ __align__(16) float g_gi1f[TMM*BB*384];
__device__ __align__(16) float g_gi1b[TMM*BB*384];
__device__ __align__(16) float g_enc1[TMM*BB*256];
__device__ __align__(16) float g_GE[NB*G3];
__device__ __align__(16) float g_Gc[TMM*BB*G3];
__device__ __align__(16) int   g_qw[TW*BB];
__device__ __align__(16) int   g_qt[TW*BB];
__device__ __align__(16) float g_WdT[DP*NB];
__device__ __align__(16) float g_WT0f[384*128];
__device__ __align__(16) float g_WT0b[384*128];
__device__ __align__(16) float g_WT1f[384*128];
__device__ __align__(16) float g_WT1b[384*128];
__device__ __align__(16) float g_WT[512*G3];
__device__ __align__(16) float g_h[2*HH*BB];
__device__ __align__(16) float g_H[(size_t)TW*BB*HH];
__device__ __align__(16) float g_o[(size_t)TW*BB*DP];
__device__ unsigned g_bar;
__device__ double   g_nll;

#define DUP2(d,s)    asm("mov.b64 %0, {%1,%1};" : "=l"(d) : "f"(s))
#define FMA2(d,a,b)  asm("fma.rn.f32x2 %0, %1, %2, %0;" : "+l"(d) : "l"(a), "l"(b))
#define UNPK(lo,hi,s) asm("mov.b64 {%0,%1}, %2;" : "=f"(lo), "=f"(hi) : "l"(s))

__device__ __forceinline__ float tanh_fast(float x) {
    float y; asm("tanh.approx.f32 %0, %1;" : "=f"(y) : "f"(x)); return y;
}
__device__ __forceinline__ float sigm_fast(float x) {
    return __fdividef(1.0f, 1.0f + __expf(-x));
}
__device__ __forceinline__ int quant(float v) {
    int q = (int)floorf((v + 1.0f) * 128.0f);
    return max(0, min(255, q));
}

// ---- prep: init + quantize + all weight transposes -----------------------
__global__ void prep_all(const float* __restrict__ y, const float* __restrict__ Wd,
                         const float* __restrict__ W0f, const float* __restrict__ W0b,
                         const float* __restrict__ W1f, const float* __restrict__ W1b,
                         const float* __restrict__ wWih)
{
    int idx = blockIdx.x * blockDim.x + threadIdx.x;
    if (idx == 0) { g_bar = 0u; g_nll = 0.0; }
    if (idx < 2*HH*BB) g_h[idx] = 0.0f;
    if (idx < TW*BB) {
        int t = idx / BB, b = idx % BB;
        g_qt[idx] = quant(y[idx]);
        float w = (t == 0) ? 0.0f : y[(t-1)*BB + b];
        g_qw[idx] = quant(w);
    }
    if (idx < DP*NB) {
        int k = idx / NB, j = idx % NB;
        g_WdT[idx] = Wd[j*DP + k];
    }
    if (idx < 384*128) {
        int r = idx >> 7, k = idx & 127;
        g_WT0f[k*384 + r] = W0f[idx];
        g_WT0b[k*384 + r] = W0b[idx];
        g_WT1f[k*384 + r] = W1f[idx];
        g_WT1b[k*384 + r] = W1b[idx];
    }
    if (idx < G3*512) {
        int r = idx >> 9, k = idx & 511;
        g_WT[(size_t)k*G3 + r] = wWih[idx];
    }
}

// ---- GE table: GE[m][r] = E[m] . wWih[r,0:256], coalesced via g_WT -------
__global__ void __launch_bounds__(256) ge_tile(const float* __restrict__ E)
{
    __shared__ float a_sm[8][256];
    int gx = blockIdx.x, tid = threadIdx.x;
    int mt = gx / 11, rt = gx - mt*11;
    int m0 = mt * 8;
#pragma unroll
    for (int i = 0; i < 8; i++) a_sm[i][tid] = E[(m0+i)*256 + tid];
    __syncthreads();
    int r = rt*256 + tid;
    if (r >= G3) return;
    float acc[8] = {0,0,0,0,0,0,0,0};
    for (int k = 0; k < 256; k++) {
        float wv = g_WT[(size_t)k*G3 + r];
#pragma unroll
        for (int i = 0; i < 8; i++) acc[i] += a_sm[i][k] * wv;
    }
#pragma unroll
    for (int i = 0; i < 8; i++) g_GE[(size_t)(m0+i)*G3 + r] = acc[i];
}

// ---- Gc table: Gc[f][r] = enc1[f] . wWih[r,256:512] + bih ----------------
__global__ void __launch_bounds__(256) gc_tile(const float* __restrict__ w_bih)
{
    __shared__ float a_sm[8][256];
    int gx = blockIdx.x, tid = threadIdx.x;
    int mt = gx / 11, rt = gx - mt*11;
    int m0 = mt * 8;
#pragma unroll
    for (int i = 0; i < 8; i++) a_sm[i][tid] = g_enc1[(m0+i)*256 + tid];
    __syncthreads();
    int r = rt*256 + tid;
    if (r >= G3) return;
    float bv = w_bih[r];
    float acc[8] = {bv,bv,bv,bv,bv,bv,bv,bv};
    for (int k = 0; k < 256; k++) {
        float wv = g_WT[(size_t)(256+k)*G3 + r];
#pragma unroll
        for (int i = 0; i < 8; i++) acc[i] += a_sm[i][k] * wv;
    }
#pragma unroll
    for (int i = 0; i < 8; i++) g_Gc[(size_t)(m0+i)*G3 + r] = acc[i];
}

// ---- warp-per-output input projection (coalesced W reads + shfl reduce) --
// layer 0: A = x (K=80); layer 1: A = g_enc0 (K=256). grid (6144, 2).
__global__ void __launch_bounds__(256) mv_warp(int layer, const float* __restrict__ x,
    const float* __restrict__ Wf, const float* __restrict__ bf,
    const float* __restrict__ Wb, const float* __restrict__ bb)
{
    int yd = blockIdx.y;
    int gwid = (blockIdx.x * 256 + threadIdx.x) >> 5;
    int lane = threadIdx.x & 31;
    if (gwid >= 128*384) return;
    int m = gwid / 384, r = gwid - m*384;
    int K = layer ? 256 : 80;
    const float* a = layer ? (g_enc0 + m*256) : (x + m*80);
    const float* w = (yd ? Wb : Wf) + r*K;
    float s = 0.0f;
    for (int k = lane; k < K; k += 32) s += a[k] * w[k];
#pragma unroll
    for (int off = 16; off; off >>= 1) s += __shfl_xor_sync(0xffffffffu, s, off);
    if (lane == 0) {
        float v = s + (yd ? bb : bf)[r];
        float* C = layer ? (yd ? g_gi1b : g_gi1f) : (yd ? g_gi0b : g_gi0f);
        C[gwid] = v;
    }
}

// ---- encoder GRU scan (fwd+bwd fused) ------------------------------------
__global__ void __launch_bounds__(384) enc_scan2(int layer,
    const float* __restrict__ bhhF, const float* __restrict__ bhhB)
{
    __shared__ float h_sm[128];
    __shared__ float gh[384];
    int b = blockIdx.x;
    int dir = blockIdx.y;
    const float* gi  = layer ? (dir ? g_gi1b : g_gi1f) : (dir ? g_gi0b : g_gi0f);
    const float* WT  = layer ? (dir ? g_WT1b : g_WT1f) : (dir ? g_WT0b : g_WT0f);
    const float* bhh = dir ? bhhB : bhhF;
    float* out = layer ? g_enc1 : g_enc0;
    int outOff = dir ? 128 : 0;
    int i = threadIdx.x;

    if (i < 128) h_sm[i] = 0.0f;
    __syncthreads();

    for (int s = 0; s < 32; s++) {
        int t = dir ? (31 - s) : s;
        float a = 0.0f;
        const float* w = WT + i;
#pragma unroll 8
        for (int k = 0; k < 128; k++)
            a += __ldg(w + k*384) * h_sm[k];
        gh[i] = a;
        __syncthreads();
        if (i < 128) {
            const float* gp = gi + (size_t)(t*BB + b) * 384;
            float r = 1.0f / (1.0f + expf(-(gp[i]       + gh[i]       + bhh[i])));
            float z = 1.0f / (1.0f + expf(-(gp[128 + i] + gh[128 + i] + bhh[128 + i])));
            float n = tanhf(gp[256 + i] + r * (gh[256 + i] + bhh[256 + i]));
            float hnew = (1.0f - z) * n + z * h_sm[i];
            h_sm[i] = hnew;
            out[(size_t)(t*BB + b) * 256 + outOff + i] = hnew;
        }
        __syncthreads();
    }
}

// ---- wav GRU chunk: CH steps, f32x2 FMAs, fast gates, backoff barrier ----
__global__ void wav_chunk(const float* __restrict__ Whh, const float* __restrict__ bhh, int t0)
{
    __shared__ float4 hs4[HH];
    __shared__ float  gh_smf[RPC*BB];
    ulonglong2* hsU = (ulonglong2*)hs4;
    float4* gh4 = (float4*)gh_smf;
    int tid = threadIdx.x, cta = blockIdx.x;
    int wid = tid >> 5, lane = tid & 31;
    int r0 = wid * 3;
    int c = t0 / CH;

    float wreg[3][28];
#pragma unroll
    for (int i = 0; i < 3; i++) {
        int lr = r0 + i;
        int g = lr >> 3, u = lr & 7;
        const float* wrow = Whh + (size_t)(g*HH + cta*UPC + u) * HH;
#pragma unroll
        for (int j = 0; j < 28; j++) wreg[i][j] = wrow[lane + 32*j];
    }

    int gu = tid >> 2, gb = tid & 3;
    float bhr = 0.f, bhz = 0.f, bhn = 0.f; int jg = 0;
    float gir = 0.f, giz = 0.f, gin = 0.f;
    if (tid < 32) {
        jg = cta*UPC + gu;
        bhr = bhh[jg]; bhz = bhh[HH + jg]; bhn = bhh[2*HH + jg];
        int q = g_qw[t0*BB + gb];
        const float* ge = g_GE + (size_t)q * G3;
        const float* gc = g_Gc + (size_t)((t0/80)*BB + gb) * G3;
        gir = ge[jg]        + gc[jg];
        giz = ge[HH + jg]   + gc[HH + jg];
        gin = ge[2*HH + jg] + gc[2*HH + jg];
    }
    __syncthreads();

    for (int s = 0; s < CH; s++) {
        int t = t0 + s;
        int cur = t & 1;

        // stage h_t (L2-only)
        const float4* hg = (const float4*)(g_h + cur * HH * BB);
        hs4[tid]       = __ldcg(hg + tid);
        hs4[tid + 256] = __ldcg(hg + tid + 256);
        hs4[tid + 512] = __ldcg(hg + tid + 512);
        if (tid < 128) hs4[tid + 768] = __ldcg(hg + tid + 768);
        __syncthreads();

        // dot in packed f32x2: rows r0..r0+2, batches (b0,b1)|(b2,b3)
        unsigned long long a0l=0, a0h=0, a1l=0, a1h=0, a2l=0, a2h=0;
#pragma unroll
        for (int j = 0; j < 28; j++) {
            ulonglong2 hv = hsU[lane + 32*j];
            unsigned long long w2;
            DUP2(w2, wreg[0][j]); FMA2(a0l, w2, hv.x); FMA2(a0h, w2, hv.y);
            DUP2(w2, wreg[1][j]); FMA2(a1l, w2, hv.x); FMA2(a1h, w2, hv.y);
            DUP2(w2, wreg[2][j]); FMA2(a2l, w2, hv.x); FMA2(a2h, w2, hv.y);
        }
        float4 a0, a1, a2;
        UNPK(a0.x, a0.y, a0l); UNPK(a0.z, a0.w, a0h);
        UNPK(a1.x, a1.y, a1l); UNPK(a1.z, a1.w, a1h);
        UNPK(a2.x, a2.y, a2l); UNPK(a2.z, a2.w, a2h);
#pragma unroll
        for (int off = 16; off; off >>= 1) {
            a0.x += __shfl_xor_sync(0xffffffffu, a0.x, off);
            a0.y += __shfl_xor_sync(0xffffffffu, a0.y, off);
            a0.z += __shfl_xor_sync(0xffffffffu, a0.z, off);
            a0.w += __shfl_xor_sync(0xffffffffu, a0.w, off);
            a1.x += __shfl_xor_sync(0xffffffffu, a1.x, off);
            a1.y += __shfl_xor_sync(0xffffffffu, a1.y, off);
            a1.z += __shfl_xor_sync(0xffffffffu, a1.z, off);
            a1.w += __shfl_xor_sync(0xffffffffu, a1.w, off);
            a2.x += __shfl_xor_sync(0xffffffffu, a2.x, off);
            a2.y += __shfl_xor_sync(0xffffffffu, a2.y, off);
            a2.z += __shfl_xor_sync(0xffffffffu, a2.z, off);
            a2.w += __shfl_xor_sync(0xffffffffu, a2.w, off);
        }
        if (lane == 0) { gh4[r0] = a0; gh4[r0+1] = a1; gh4[r0+2] = a2; }
        __syncthreads();

        // gate combine (fast MUFU math) + publish h_{t+1}
        if (tid < 32) {
            float ghr = gh_smf[gu*4 + gb];
            float ghz = gh_smf[(UPC + gu)*4 + gb];
            float ghn = gh_smf[(2*UPC + gu)*4 + gb];
            float rg = sigm_fast(gir + ghr + bhr);
            float zg = sigm_fast(giz + ghz + bhz);
            float ng = tanh_fast(gin + rg * (ghn + bhn));
            float4 hold4 = hs4[jg];
            float hold = (gb == 0) ? hold4.x : (gb == 1) ? hold4.y : (gb == 2) ? hold4.z : hold4.w;
            float hnew = (1.0f - zg) * ng + zg * hold;
            __stcg(g_h + (cur^1) * HH * BB + jg*4 + gb, hnew);
            g_H[(size_t)(t*BB + gb) * HH + jg] = hnew;
        }

        if (s < CH-1) {
            if (tid < 32) {
                if (tid == 0) {
                    unsigned one = 1u;
                    asm volatile("red.release.gpu.global.add.u32 [%0], %1;"
                                 :: "l"(&g_bar), "r"(one) : "memory");
                }
                // overlap next-step gi gather with barrier wait
                {
                    int tn = t + 1;
                    int q = g_qw[tn*BB + gb];
                    const float* ge = g_GE + (size_t)q * G3;
                    const float* gc = g_Gc + (size_t)((tn/80)*BB + gb) * G3;
                    gir = ge[jg]        + gc[jg];
                    giz = ge[HH + jg]   + gc[HH + jg];
                    gin = ge[2*HH + jg] + gc[2*HH + jg];
                }
                unsigned target = (unsigned)NCTA * (unsigned)(c*(CH-1) + s + 1);
                unsigned v = 0, guard = 0;
                asm volatile("ld.acquire.gpu.global.u32 %0, [%1];"
                             : "=r"(v) : "l"(&g_bar) : "memory");
                while (v < target && ++guard < 200000u) {
                    __nanosleep(40);
                    asm volatile("ld.acquire.gpu.global.u32 %0, [%1];"
                                 : "=r"(v) : "l"(&g_bar) : "memory");
                }
            }
            __syncthreads();
        }
    }
}

// ---- projection + GELU, 128x64 tiles -------------------------------------
__global__ void __launch_bounds__(256) gemm_gelu(const float* __restrict__ B,
                                                 const float* __restrict__ bias)
{
    __shared__ float As[16][132];
    __shared__ float Bs[16][68];
    int tid = threadIdx.x;
    int n0 = blockIdx.x * 64, m0 = blockIdx.y * 128;
    int tx = tid & 15, ty = tid >> 4;

    float acc[8][4];
#pragma unroll
    for (int i = 0; i < 8; i++)
#pragma unroll
        for (int j = 0; j < 4; j++) acc[i][j] = 0.0f;

    int ar = tid >> 1, ak = (tid & 1) * 8;
    int br = tid >> 2, bk = (tid & 3) * 4;

    for (int kt = 0; kt < HH; kt += 16) {
        {
            const float* ap = g_H + (size_t)(m0 + ar) * HH + kt + ak;
            float4 v0 = *(const float4*)ap;
            float4 v1 = *(const float4*)(ap + 4);
            As[ak+0][ar] = v0.x; As[ak+1][ar] = v0.y;
            As[ak+2][ar] = v0.z; As[ak+3][ar] = v0.w;
            As[ak+4][ar] = v1.x; As[ak+5][ar] = v1.y;
            As[ak+6][ar] = v1.z; As[ak+7][ar] = v1.w;
        }
        {
            float4 v = *(const float4*)(B + (size_t)(n0 + br) * HH + kt + bk);
            Bs[bk+0][br] = v.x; Bs[bk+1][br] = v.y;
            Bs[bk+2][br] = v.z; Bs[bk+3][br] = v.w;
        }
        __syncthreads();
#pragma unroll
        for (int k = 0; k < 16; k++) {
            float a[8], b[4];
#pragma unroll
            for (int i = 0; i < 8; i++) a[i] = As[k][ty*8 + i];
#pragma unroll
            for (int j = 0; j < 4; j++) b[j] = Bs[k][tx*4 + j];
#pragma unroll
            for (int i = 0; i < 8; i++)
#pragma unroll
                for (int j = 0; j < 4; j++) acc[i][j] += a[i] * b[j];
        }
        __syncthreads();
    }
#pragma unroll
    for (int j = 0; j < 4; j++) {
        float bv = bias[n0 + tx*4 + j];
#pragma unroll
        for (int i = 0; i < 8; i++) {
            float v = acc[i][j] + bv;
            v = 0.5f * v * (1.0f + erff(v * 0.70710678118654752f));
            g_o[(size_t)(m0 + ty*8 + i) * DP + n0 + tx*4 + j] = v;
        }
    }
}

// ---- fused logits + log_softmax + NLL ------------------------------------
__global__ void __launch_bounds__(256) nll_kernel(const float* __restrict__ bd)
{
    __shared__ float o_sm[8*DP];
    __shared__ float lg[8*NB];
    int tid = threadIdx.x;
    int m0 = blockIdx.x * 8;

    const float4* op = (const float4*)(g_o + (size_t)m0 * DP);
    float4* os4 = (float4*)o_sm;
    for (int idx = tid; idx < 8*DP/4; idx += 256) os4[idx] = op[idx];
    __syncthreads();

    float acc[8];
    float bdv = bd[tid];
#pragma unroll
    for (int r = 0; r < 8; r++) acc[r] = bdv;

    for (int k = 0; k < DP; k += 4) {
        float w0 = g_WdT[(k+0)*NB + tid];
        float w1 = g_WdT[(k+1)*NB + tid];
        float w2 = g_WdT[(k+2)*NB + tid];
        float w3 = g_WdT[(k+3)*NB + tid];
#pragma unroll
        for (int r = 0; r < 8; r++) {
            float4 o4 = *(const float4*)&o_sm[r*DP + k];
            acc[r] += w0*o4.x + w1*o4.y + w2*o4.z + w3*o4.w;
        }
    }
#pragma unroll
    for (int r = 0; r < 8; r++) lg[r*NB + tid] = acc[r];
    __syncthreads();

    int wid = tid >> 5, lane = tid & 31;
    {
        int r = wid;
        float m = -1e30f;
#pragma unroll
        for (int i = 0; i < 8; i++) m = fmaxf(m, lg[r*NB + lane + i*32]);
#pragma unroll
        for (int off = 16; off; off >>= 1) m = fmaxf(m, __shfl_xor_sync(0xffffffffu, m, off));
        float s = 0.f;
#pragma unroll
        for (int i = 0; i < 8; i++) s += expf(lg[r*NB + lane + i*32] - m);
#pragma unroll
        for (int off = 16; off; off >>= 1) s += __shfl_xor_sync(0xffffffffu, s, off);
        if (lane == 0) {
            int row = m0 + r;
            int tgt = g_qt[row];
            float nllr = (m + logf(s)) - lg[r*NB + tgt];
            atomicAdd(&g_nll, (double)nllr);
        }
    }
}

// ---- finalize with 8-bit liveness diagnostic -------------------------------
__global__ void finalize_kernel(float* out) {
    float p[8] = {0,0,0,0,0,0,0,0};
#pragma unroll
    for (int i = 0; i < 8; i++) {
        p[0] += fabsf(g_WT0f[i * 6143 + 5]);
        p[1] += fabsf(g_gi0f[i * 6143 + 9]);
        p[2] += fabsf(g_enc0[i * 4093 + 3]);
        p[3] += fabsf(g_enc1[i * 4093 + 3]);
        p[4] += fabsf(g_GE[(size_t)i * 86011 + 7]);
        p[5] += fabsf(g_Gc[(size_t)i * 43007 + 1]);
        p[6] += fabsf(g_H[(size_t)i * 1111111 + 13]);
        p[7] += fabsf(g_o[(size_t)i * 654321 + 11]);
    }
    int F = 0;
#pragma unroll
    for (int i = 0; i < 8; i++) if (p[i] > 0.f) F |= (1 << i);
    if (F == 255) out[0] = (float)(g_nll / (double)(TW * BB));
    else          out[0] = 1000.0f + (float)F;
}

extern "C" void kernel_launch(void* const* d_in, const int* in_sizes, int n_in,
                              void* d_out, int out_size)
{
    const float* x        = (const float*)d_in[0];
    const float* y        = (const float*)d_in[1];
    const float* m0f_Wih  = (const float*)d_in[2];
    const float* m0f_Whh  = (const float*)d_in[3];
    const float* m0f_bih  = (const float*)d_in[4];
    const float* m0f_bhh  = (const float*)d_in[5];
    const float* m0b_Wih  = (const float*)d_in[6];
    const float* m0b_Whh  = (const float*)d_in[7];
    const float* m0b_bih  = (const float*)d_in[8];
    const float* m0b_bhh  = (const float*)d_in[9];
    const float* m1f_Wih  = (const float*)d_in[10];
    const float* m1f_Whh  = (const float*)d_in[11];
    const float* m1f_bih  = (const float*)d_in[12];
    const float* m1f_bhh  = (const float*)d_in[13];
    const float* m1b_Wih  = (const float*)d_in[14];
    const float* m1b_Whh  = (const float*)d_in[15];
    const float* m1b_bih  = (const float*)d_in[16];
    const float* m1b_bhh  = (const float*)d_in[17];
    const float* w_Wih    = (const float*)d_in[18];
    const float* w_Whh    = (const float*)d_in[19];
    const float* w_bih    = (const float*)d_in[20];
    const float* w_bhh    = (const float*)d_in[21];
    const float* Wp       = (const float*)d_in[22];
    const float* bp       = (const float*)d_in[23];
    const float* E        = (const float*)d_in[24];
    const float* Wd       = (const float*)d_in[25];
    const float* bd       = (const float*)d_in[26];

    prep_all<<<(G3*512 + 255)/256, 256>>>(y, Wd, m0f_Whh, m0b_Whh, m1f_Whh, m1b_Whh, w_Wih);
    ge_tile<<<352, 256>>>(E);
    mv_warp<<<dim3(6144, 2), 256>>>(0, x, m0f_Wih, m0f_bih, m0b_Wih, m0b_bih);
    enc_scan2<<<dim3(BB, 2), 384>>>(0, m0f_bhh, m0b_bhh);
    mv_warp<<<dim3(6144, 2), 256>>>(1, x, m1f_Wih, m1f_bih, m1b_Wih, m1b_bih);
    enc_scan2<<<dim3(BB, 2), 384>>>(1, m1f_bhh, m1b_bhh);
    gc_tile<<<176, 256>>>(w_bih);

    for (int c = 0; c < TW/CH; c++)
        wav_chunk<<<NCTA, 256>>>(w_Whh, w_bhh, c*CH);

    gemm_gelu<<<dim3(DP/64, (TW*BB)/128), 256>>>(Wp, bp);
    nll_kernel<<<(TW*BB)/8, 256>>>(bd);
    finalize_kernel<<<1, 1>>>((float*)d_out);
}

// round 17
// speedup vs baseline: 1.7020x; 1.0134x over previous
#include <cuda_runtime.h>
#include <math.h>

#define TW 2560
#define TMM 32
#define BB 4
#define HH 896
#define G3 2688
#define NB 256
#define DP 512
#define NCTA 112
#define UPC 8
#define RPC 24

__device__ __align__(16) float g_gi0f[TMM*BB*384];
__device__ __align__(16) float g_gi0b[TMM*BB*384];
__device__ __align__(16) float g_enc0[TMM*BB*256];
__device__ __align__(16) float g_gi1f[TMM*BB*384];
__device__ __align__(16) float g_gi1b[TMM*BB*384];
__device__ __align__(16) float g_enc1[TMM*BB*256];
__device__ __align__(16) float g_GE[NB*G3];
__device__ __align__(16) float g_Gc[TMM*BB*G3];
__device__ __align__(16) int   g_qw[TW*BB];
__device__ __align__(16) int   g_qt[TW*BB];
__device__ __align__(16) float g_WdT[DP*NB];
__device__ __align__(16) float g_WT0f[384*128];
__device__ __align__(16) float g_WT0b[384*128];
__device__ __align__(16) float g_WT1f[384*128];
__device__ __align__(16) float g_WT1b[384*128];
__device__ __align__(16) float g_WT[512*G3];
__device__ __align__(16) float g_h[2*HH*BB];
__device__ __align__(16) float g_H[(size_t)TW*BB*HH];
__device__ __align__(16) float g_o[(size_t)TW*BB*DP];
__device__ unsigned g_bar;
__device__ double   g_nll;

#define DUP2(d,s)    asm("mov.b64 %0, {%1,%1};" : "=l"(d) : "f"(s))
#define FMA2(d,a,b)  asm("fma.rn.f32x2 %0, %1, %2, %0;" : "+l"(d) : "l"(a), "l"(b))
#define UNPK(lo,hi,s) asm("mov.b64 {%0,%1}, %2;" : "=f"(lo), "=f"(hi) : "l"(s))

__device__ __forceinline__ float tanh_fast(float x) {
    float y; asm("tanh.approx.f32 %0, %1;" : "=f"(y) : "f"(x)); return y;
}
__device__ __forceinline__ float sigm_fast(float x) {
    return __fdividef(1.0f, 1.0f + __expf(-x));
}
__device__ __forceinline__ int quant(float v) {
    int q = (int)floorf((v + 1.0f) * 128.0f);
    return max(0, min(255, q));
}

extern __shared__ float sdyn[];

// ---- prep: init + quantize + all weight transposes -----------------------
__global__ void prep_all(const float* __restrict__ y, const float* __restrict__ Wd,
                         const float* __restrict__ W0f, const float* __restrict__ W0b,
                         const float* __restrict__ W1f, const float* __restrict__ W1b,
                         const float* __restrict__ wWih)
{
    int idx = blockIdx.x * blockDim.x + threadIdx.x;
    if (idx == 0) { g_bar = 0u; g_nll = 0.0; }
    if (idx < 2*HH*BB) g_h[idx] = 0.0f;
    if (idx < TW*BB) {
        int t = idx / BB, b = idx % BB;
        g_qt[idx] = quant(y[idx]);
        float w = (t == 0) ? 0.0f : y[(t-1)*BB + b];
        g_qw[idx] = quant(w);
    }
    if (idx < DP*NB) {
        int k = idx / NB, j = idx % NB;
        g_WdT[idx] = Wd[j*DP + k];
    }
    if (idx < 384*128) {
        int r = idx >> 7, k = idx & 127;
        g_WT0f[k*384 + r] = W0f[idx];
        g_WT0b[k*384 + r] = W0b[idx];
        g_WT1f[k*384 + r] = W1f[idx];
        g_WT1b[k*384 + r] = W1b[idx];
    }
    if (idx < G3*512) {
        int r = idx >> 9, k = idx & 511;
        g_WT[(size_t)k*G3 + r] = wWih[idx];
    }
}

// ---- GE table ------------------------------------------------------------
__global__ void __launch_bounds__(256) ge_tile(const float* __restrict__ E)
{
    __shared__ float a_sm[8][256];
    int gx = blockIdx.x, tid = threadIdx.x;
    int mt = gx / 11, rt = gx - mt*11;
    int m0 = mt * 8;
#pragma unroll
    for (int i = 0; i < 8; i++) a_sm[i][tid] = E[(m0+i)*256 + tid];
    __syncthreads();
    int r = rt*256 + tid;
    if (r >= G3) return;
    float acc[8] = {0,0,0,0,0,0,0,0};
    for (int k = 0; k < 256; k++) {
        float wv = g_WT[(size_t)k*G3 + r];
#pragma unroll
        for (int i = 0; i < 8; i++) acc[i] += a_sm[i][k] * wv;
    }
#pragma unroll
    for (int i = 0; i < 8; i++) g_GE[(size_t)(m0+i)*G3 + r] = acc[i];
}

// ---- Gc table ------------------------------------------------------------
__global__ void __launch_bounds__(256) gc_tile(const float* __restrict__ w_bih)
{
    __shared__ float a_sm[8][256];
    int gx = blockIdx.x, tid = threadIdx.x;
    int mt = gx / 11, rt = gx - mt*11;
    int m0 = mt * 8;
#pragma unroll
    for (int i = 0; i < 8; i++) a_sm[i][tid] = g_enc1[(m0+i)*256 + tid];
    __syncthreads();
    int r = rt*256 + tid;
    if (r >= G3) return;
    float bv = w_bih[r];
    float acc[8] = {bv,bv,bv,bv,bv,bv,bv,bv};
    for (int k = 0; k < 256; k++) {
        float wv = g_WT[(size_t)(256+k)*G3 + r];
#pragma unroll
        for (int i = 0; i < 8; i++) acc[i] += a_sm[i][k] * wv;
    }
#pragma unroll
    for (int i = 0; i < 8; i++) g_Gc[(size_t)(m0+i)*G3 + r] = acc[i];
}

// ---- warp-per-output input projection ------------------------------------
__global__ void __launch_bounds__(256) mv_warp(int layer, const float* __restrict__ x,
    const float* __restrict__ Wf, const float* __restrict__ bf,
    const float* __restrict__ Wb, const float* __restrict__ bb)
{
    int yd = blockIdx.y;
    int gwid = (blockIdx.x * 256 + threadIdx.x) >> 5;
    int lane = threadIdx.x & 31;
    if (gwid >= 128*384) return;
    int m = gwid / 384, r = gwid - m*384;
    int K = layer ? 256 : 80;
    const float* a = layer ? (g_enc0 + m*256) : (x + m*80);
    const float* w = (yd ? Wb : Wf) + r*K;
    float s = 0.0f;
    for (int k = lane; k < K; k += 32) s += a[k] * w[k];
#pragma unroll
    for (int off = 16; off; off >>= 1) s += __shfl_xor_sync(0xffffffffu, s, off);
    if (lane == 0) {
        float v = s + (yd ? bb : bf)[r];
        float* C = layer ? (yd ? g_gi1b : g_gi1f) : (yd ? g_gi0b : g_gi0f);
        C[gwid] = v;
    }
}

// ---- encoder GRU scan, weights SMEM-resident (196,608 B dynamic) ---------
__global__ void __launch_bounds__(384) enc_scan2(int layer,
    const float* __restrict__ bhhF, const float* __restrict__ bhhB)
{
    float* ws = sdyn;                  // [k=128][r=384], conflict-free
    __shared__ float h_sm[128];
    __shared__ float gh[384];
    int b = blockIdx.x;
    int dir = blockIdx.y;
    const float* gi  = layer ? (dir ? g_gi1b : g_gi1f) : (dir ? g_gi0b : g_gi0f);
    const float* WT  = layer ? (dir ? g_WT1b : g_WT1f) : (dir ? g_WT0b : g_WT0f);
    const float* bhh = dir ? bhhB : bhhF;
    float* out = layer ? g_enc1 : g_enc0;
    int outOff = dir ? 128 : 0;
    int i = threadIdx.x;

    // load W into SMEM once (coalesced float4)
    {
        const float4* src = (const float4*)WT;
        float4* dst = (float4*)ws;
        for (int idx = i; idx < 384*128/4; idx += 384) dst[idx] = src[idx];
    }
    if (i < 128) h_sm[i] = 0.0f;
    __syncthreads();

    for (int s = 0; s < 32; s++) {
        int t = dir ? (31 - s) : s;
        float a = 0.0f;
        const float* w = ws + i;
#pragma unroll 8
        for (int k = 0; k < 128; k++)
            a += w[k*384] * h_sm[k];
        gh[i] = a;
        __syncthreads();
        if (i < 128) {
            const float* gp = gi + (size_t)(t*BB + b) * 384;
            float r = 1.0f / (1.0f + expf(-(gp[i]       + gh[i]       + bhh[i])));
            float z = 1.0f / (1.0f + expf(-(gp[128 + i] + gh[128 + i] + bhh[128 + i])));
            float n = tanhf(gp[256 + i] + r * (gh[256 + i] + bhh[256 + i]));
            float hnew = (1.0f - z) * n + z * h_sm[i];
            h_sm[i] = hnew;
            out[(size_t)(t*BB + b) * 256 + outOff + i] = hnew;
        }
        __syncthreads();
    }
}

// ---- wav GRU: ONE persistent launch, all 2560 steps, 2559 grid barriers ---
__global__ void wav_all(const float* __restrict__ Whh, const float* __restrict__ bhh)
{
    __shared__ float4 hs4[HH];
    __shared__ float  gh_smf[RPC*BB];
    ulonglong2* hsU = (ulonglong2*)hs4;
    float4* gh4 = (float4*)gh_smf;
    int tid = threadIdx.x, cta = blockIdx.x;
    int wid = tid >> 5, lane = tid & 31;
    int r0 = wid * 3;

    float wreg[3][28];
#pragma unroll
    for (int i = 0; i < 3; i++) {
        int lr = r0 + i;
        int g = lr >> 3, u = lr & 7;
        const float* wrow = Whh + (size_t)(g*HH + cta*UPC + u) * HH;
#pragma unroll
        for (int j = 0; j < 28; j++) wreg[i][j] = wrow[lane + 32*j];
    }

    int gu = tid >> 2, gb = tid & 3;
    float bhr = 0.f, bhz = 0.f, bhn = 0.f; int jg = 0;
    float gir = 0.f, giz = 0.f, gin = 0.f;
    if (tid < 32) {
        jg = cta*UPC + gu;
        bhr = bhh[jg]; bhz = bhh[HH + jg]; bhn = bhh[2*HH + jg];
        int q = g_qw[gb];
        const float* ge = g_GE + (size_t)q * G3;
        const float* gc = g_Gc + (size_t)gb * G3;
        gir = ge[jg]        + gc[jg];
        giz = ge[HH + jg]   + gc[HH + jg];
        gin = ge[2*HH + jg] + gc[2*HH + jg];
    }
    __syncthreads();

    for (int t = 0; t < TW; t++) {
        int cur = t & 1;

        // stage h_t (L2-only)
        const float4* hg = (const float4*)(g_h + cur * HH * BB);
        hs4[tid]       = __ldcg(hg + tid);
        hs4[tid + 256] = __ldcg(hg + tid + 256);
        hs4[tid + 512] = __ldcg(hg + tid + 512);
        if (tid < 128) hs4[tid + 768] = __ldcg(hg + tid + 768);
        __syncthreads();

        // dot in packed f32x2
        unsigned long long a0l=0, a0h=0, a1l=0, a1h=0, a2l=0, a2h=0;
#pragma unroll
        for (int j = 0; j < 28; j++) {
            ulonglong2 hv = hsU[lane + 32*j];
            unsigned long long w2;
            DUP2(w2, wreg[0][j]); FMA2(a0l, w2, hv.x); FMA2(a0h, w2, hv.y);
            DUP2(w2, wreg[1][j]); FMA2(a1l, w2, hv.x); FMA2(a1h, w2, hv.y);
            DUP2(w2, wreg[2][j]); FMA2(a2l, w2, hv.x); FMA2(a2h, w2, hv.y);
        }
        float4 a0, a1, a2;
        UNPK(a0.x, a0.y, a0l); UNPK(a0.z, a0.w, a0h);
        UNPK(a1.x, a1.y, a1l); UNPK(a1.z, a1.w, a1h);
        UNPK(a2.x, a2.y, a2l); UNPK(a2.z, a2.w, a2h);
#pragma unroll
        for (int off = 16; off; off >>= 1) {
            a0.x += __shfl_xor_sync(0xffffffffu, a0.x, off);
            a0.y += __shfl_xor_sync(0xffffffffu, a0.y, off);
            a0.z += __shfl_xor_sync(0xffffffffu, a0.z, off);
            a0.w += __shfl_xor_sync(0xffffffffu, a0.w, off);
            a1.x += __shfl_xor_sync(0xffffffffu, a1.x, off);
            a1.y += __shfl_xor_sync(0xffffffffu, a1.y, off);
            a1.z += __shfl_xor_sync(0xffffffffu, a1.z, off);
            a1.w += __shfl_xor_sync(0xffffffffu, a1.w, off);
            a2.x += __shfl_xor_sync(0xffffffffu, a2.x, off);
            a2.y += __shfl_xor_sync(0xffffffffu, a2.y, off);
            a2.z += __shfl_xor_sync(0xffffffffu, a2.z, off);
            a2.w += __shfl_xor_sync(0xffffffffu, a2.w, off);
        }
        if (lane == 0) { gh4[r0] = a0; gh4[r0+1] = a1; gh4[r0+2] = a2; }
        __syncthreads();

        // gates + publish h_{t+1}
        if (tid < 32) {
            float ghr = gh_smf[gu*4 + gb];
            float ghz = gh_smf[(UPC + gu)*4 + gb];
            float ghn = gh_smf[(2*UPC + gu)*4 + gb];
            float rg = sigm_fast(gir + ghr + bhr);
            float zg = sigm_fast(giz + ghz + bhz);
            float ng = tanh_fast(gin + rg * (ghn + bhn));
            float4 hold4 = hs4[jg];
            float hold = (gb == 0) ? hold4.x : (gb == 1) ? hold4.y : (gb == 2) ? hold4.z : hold4.w;
            float hnew = (1.0f - zg) * ng + zg * hold;
            __stcg(g_h + (cur^1) * HH * BB + jg*4 + gb, hnew);
            g_H[(size_t)(t*BB + gb) * HH + jg] = hnew;
        }

        if (t < TW-1) {
            if (tid < 32) {
                if (tid == 0) {
                    unsigned one = 1u;
                    asm volatile("red.release.gpu.global.add.u32 [%0], %1;"
                                 :: "l"(&g_bar), "r"(one) : "memory");
                }
                // overlap next-step gi gather with barrier wait
                {
                    int tn = t + 1;
                    int q = g_qw[tn*BB + gb];
                    const float* ge = g_GE + (size_t)q * G3;
                    const float* gc = g_Gc + (size_t)((tn/80)*BB + gb) * G3;
                    gir = ge[jg]        + gc[jg];
                    giz = ge[HH + jg]   + gc[HH + jg];
                    gin = ge[2*HH + jg] + gc[2*HH + jg];
                }
                unsigned target = (unsigned)NCTA * (unsigned)(t + 1);
                unsigned v = 0, guard = 0;
                asm volatile("ld.acquire.gpu.global.u32 %0, [%1];"
                             : "=r"(v) : "l"(&g_bar) : "memory");
                while (v < target && ++guard < 200000u) {
                    __nanosleep(40);
                    asm volatile("ld.acquire.gpu.global.u32 %0, [%1];"
                                 : "=r"(v) : "l"(&g_bar) : "memory");
                }
            }
            __syncthreads();
        }
    }
}

// ---- projection + GELU, 128x64 tiles -------------------------------------
__global__ void __launch_bounds__(256) gemm_gelu(const float* __restrict__ B,
                                                 const float* __restrict__ bias)
{
    __shared__ float As[16][132];
    __shared__ float Bs[16][68];
    int tid = threadIdx.x;
    int n0 = blockIdx.x * 64, m0 = blockIdx.y * 128;
    int tx = tid & 15, ty = tid >> 4;

    float acc[8][4];
#pragma unroll
    for (int i = 0; i < 8; i++)
#pragma unroll
        for (int j = 0; j < 4; j++) acc[i][j] = 0.0f;

    int ar = tid >> 1, ak = (tid & 1) * 8;
    int br = tid >> 2, bk = (tid & 3) * 4;

    for (int kt = 0; kt < HH; kt += 16) {
        {
            const float* ap = g_H + (size_t)(m0 + ar) * HH + kt + ak;
            float4 v0 = *(const float4*)ap;
            float4 v1 = *(const float4*)(ap + 4);
            As[ak+0][ar] = v0.x; As[ak+1][ar] = v0.y;
            As[ak+2][ar] = v0.z; As[ak+3][ar] = v0.w;
            As[ak+4][ar] = v1.x; As[ak+5][ar] = v1.y;
            As[ak+6][ar] = v1.z; As[ak+7][ar] = v1.w;
        }
        {
            float4 v = *(const float4*)(B + (size_t)(n0 + br) * HH + kt + bk);
            Bs[bk+0][br] = v.x; Bs[bk+1][br] = v.y;
            Bs[bk+2][br] = v.z; Bs[bk+3][br] = v.w;
        }
        __syncthreads();
#pragma unroll
        for (int k = 0; k < 16; k++) {
            float a[8], b[4];
#pragma unroll
            for (int i = 0; i < 8; i++) a[i] = As[k][ty*8 + i];
#pragma unroll
            for (int j = 0; j < 4; j++) b[j] = Bs[k][tx*4 + j];
#pragma unroll
            for (int i = 0; i < 8; i++)
#pragma unroll
                for (int j = 0; j < 4; j++) acc[i][j] += a[i] * b[j];
        }
        __syncthreads();
    }
#pragma unroll
    for (int j = 0; j < 4; j++) {
        float bv = bias[n0 + tx*4 + j];
#pragma unroll
        for (int i = 0; i < 8; i++) {
            float v = acc[i][j] + bv;
            v = 0.5f * v * (1.0f + erff(v * 0.70710678118654752f));
            g_o[(size_t)(m0 + ty*8 + i) * DP + n0 + tx*4 + j] = v;
        }
    }
}

// ---- fused logits + log_softmax + NLL ------------------------------------
__global__ void __launch_bounds__(256) nll_kernel(const float* __restrict__ bd)
{
    __shared__ float o_sm[8*DP];
    __shared__ float lg[8*NB];
    int tid = threadIdx.x;
    int m0 = blockIdx.x * 8;

    const float4* op = (const float4*)(g_o + (size_t)m0 * DP);
    float4* os4 = (float4*)o_sm;
    for (int idx = tid; idx < 8*DP/4; idx += 256) os4[idx] = op[idx];
    __syncthreads();

    float acc[8];
    float bdv = bd[tid];
#pragma unroll
    for (int r = 0; r < 8; r++) acc[r] = bdv;

    for (int k = 0; k < DP; k += 4) {
        float w0 = g_WdT[(k+0)*NB + tid];
        float w1 = g_WdT[(k+1)*NB + tid];
        float w2 = g_WdT[(k+2)*NB + tid];
        float w3 = g_WdT[(k+3)*NB + tid];
#pragma unroll
        for (int r = 0; r < 8; r++) {
            float4 o4 = *(const float4*)&o_sm[r*DP + k];
            acc[r] += w0*o4.x + w1*o4.y + w2*o4.z + w3*o4.w;
        }
    }
#pragma unroll
    for (int r = 0; r < 8; r++) lg[r*NB + tid] = acc[r];
    __syncthreads();

    int wid = tid >> 5, lane = tid & 31;
    {
        int r = wid;
        float m = -1e30f;
#pragma unroll
        for (int i = 0; i < 8; i++) m = fmaxf(m, lg[r*NB + lane + i*32]);
#pragma unroll
        for (int off = 16; off; off >>= 1) m = fmaxf(m, __shfl_xor_sync(0xffffffffu, m, off));
        float s = 0.f;
#pragma unroll
        for (int i = 0; i < 8; i++) s += expf(lg[r*NB + lane + i*32] - m);
#pragma unroll
        for (int off = 16; off; off >>= 1) s += __shfl_xor_sync(0xffffffffu, s, off);
        if (lane == 0) {
            int row = m0 + r;
            int tgt = g_qt[row];
            float nllr = (m + logf(s)) - lg[r*NB + tgt];
            atomicAdd(&g_nll, (double)nllr);
        }
    }
}

// ---- finalize with 8-bit liveness diagnostic -------------------------------
__global__ void finalize_kernel(float* out) {
    float p[8] = {0,0,0,0,0,0,0,0};
#pragma unroll
    for (int i = 0; i < 8; i++) {
        p[0] += fabsf(g_WT0f[i * 6143 + 5]);
        p[1] += fabsf(g_gi0f[i * 6143 + 9]);
        p[2] += fabsf(g_enc0[i * 4093 + 3]);
        p[3] += fabsf(g_enc1[i * 4093 + 3]);
        p[4] += fabsf(g_GE[(size_t)i * 86011 + 7]);
        p[5] += fabsf(g_Gc[(size_t)i * 43007 + 1]);
        p[6] += fabsf(g_H[(size_t)i * 1111111 + 13]);
        p[7] += fabsf(g_o[(size_t)i * 654321 + 11]);
    }
    int F = 0;
#pragma unroll
    for (int i = 0; i < 8; i++) if (p[i] > 0.f) F |= (1 << i);
    if (F == 255) out[0] = (float)(g_nll / (double)(TW * BB));
    else          out[0] = 1000.0f + (float)F;
}

extern "C" void kernel_launch(void* const* d_in, const int* in_sizes, int n_in,
                              void* d_out, int out_size)
{
    const float* x        = (const float*)d_in[0];
    const float* y        = (const float*)d_in[1];
    const float* m0f_Wih  = (const float*)d_in[2];
    const float* m0f_Whh  = (const float*)d_in[3];
    const float* m0f_bih  = (const float*)d_in[4];
    const float* m0f_bhh  = (const float*)d_in[5];
    const float* m0b_Wih  = (const float*)d_in[6];
    const float* m0b_Whh  = (const float*)d_in[7];
    const float* m0b_bih  = (const float*)d_in[8];
    const float* m0b_bhh  = (const float*)d_in[9];
    const float* m1f_Wih  = (const float*)d_in[10];
    const float* m1f_Whh  = (const float*)d_in[11];
    const float* m1f_bih  = (const float*)d_in[12];
    const float* m1f_bhh  = (const float*)d_in[13];
    const float* m1b_Wih  = (const float*)d_in[14];
    const float* m1b_Whh  = (const float*)d_in[15];
    const float* m1b_bih  = (const float*)d_in[16];
    const float* m1b_bhh  = (const float*)d_in[17];
    const float* w_Wih    = (const float*)d_in[18];
    const float* w_Whh    = (const float*)d_in[19];
    const float* w_bih    = (const float*)d_in[20];
    const float* w_bhh    = (const float*)d_in[21];
    const float* Wp       = (const float*)d_in[22];
    const float* bp       = (const float*)d_in[23];
    const float* E        = (const float*)d_in[24];
    const float* Wd       = (const float*)d_in[25];
    const float* bd       = (const float*)d_in[26];

    const int ENC_SMEM = 384*128*4;   // 196,608 B
    cudaFuncSetAttribute(enc_scan2, cudaFuncAttributeMaxDynamicSharedMemorySize, ENC_SMEM);

    prep_all<<<(G3*512 + 255)/256, 256>>>(y, Wd, m0f_Whh, m0b_Whh, m1f_Whh, m1b_Whh, w_Wih);
    ge_tile<<<352, 256>>>(E);
    mv_warp<<<dim3(6144, 2), 256>>>(0, x, m0f_Wih, m0f_bih, m0b_Wih, m0b_bih);
    enc_scan2<<<dim3(BB, 2), 384, ENC_SMEM>>>(0, m0f_bhh, m0b_bhh);
    mv_warp<<<dim3(6144, 2), 256>>>(1, x, m1f_Wih, m1f_bih, m1b_Wih, m1b_bih);
    enc_scan2<<<dim3(BB, 2), 384, ENC_SMEM>>>(1, m1f_bhh, m1b_bhh);
    gc_tile<<<176, 256>>>(w_bih);

    // recurrence: ONE persistent launch, internal monotonic grid barriers
    wav_all<<<NCTA, 256>>>(w_Whh, w_bhh);

    gemm_gelu<<<dim3(DP/64, (TW*BB)/128), 256>>>(Wp, bp);
    nll_kernel<<<(TW*BB)/8, 256>>>(bd);
    finalize_kernel<<<1, 1>>>((float*)d_out);
}